// round 2
// baseline (speedup 1.0000x reference)
#include <cuda_runtime.h>
#include <cuda_bf16.h>

// WeaveLayer: pure permutation
//   out[b, yb*8 + hi*4 + px, xb*8 + wi*4 + py] = in[b, yb*4 + py, xb*4 + px, q=2*hi+wi]
// Shapes fixed by the problem: in (32, 768, 768, 4) f32, out (32, 1536, 1536, 1) f32, n=4.
//
// Strategy: smem-staged transpose. CTA = (b, yb, x-half).
//  - Load: 4 input rows x 384 pixels; each pixel = one float4 (4 channels) -> LDG.128 coalesced.
//  - Scatter the 4 channels into an smem tile in OUTPUT layout (8 rows x 768 cols, stride 772
//    for 16B-aligned rows + bank spreading; min 2-way STS conflict, hidden under HBM).
//  - Store: 8 output row segments x 768 floats as coalesced float4 STG.

#define B_      32
#define Ydim    768
#define Xdim    768
#define YB      192          // Ydim / 4
#define XHALF   384          // pixels per x-half
#define STRIDE  772          // 768 + 4 pad: multiple of 4 (float4 LDS), stride%32=4 (bank spread)
#define THREADS 256

__global__ __launch_bounds__(THREADS) void weave_kernel(
    const float4* __restrict__ in4,   // (32, 768, 768, 4) viewed as float4 per pixel
    float4* __restrict__ out4)        // (32, 1536, 1536) viewed as float4
{
    __shared__ float smem[8 * STRIDE];   // 24704 bytes

    const int bid = blockIdx.x;
    const int xh  = bid & 1;                 // x-half: 0 or 1
    const int yb  = (bid >> 1) % YB;         // 0..191
    const int b   = bid / (2 * YB);          // 0..31

    const int tid = threadIdx.x;

    // ---- Load pass: 4 input rows (y = yb*4 + py), x in [xh*384, xh*384+384) ----
    // float4 index base: pixel (b, y, x) -> b*768*768 + y*768 + x
    const int in_base = (b * Ydim + yb * 4) * Xdim + xh * XHALF;

    #pragma unroll
    for (int k = 0; k < 6; k++) {
        const int i  = tid + k * THREADS;    // 0..1535 = 4 rows * 384 px
        const int py = i / XHALF;            // 0..3
        const int xl = i - py * XHALF;       // 0..383 (local x)
        const float4 v = in4[in_base + py * Xdim + xl];

        const int px  = xl & 3;
        const int xbl = xl >> 2;             // local xb: 0..95
        const int colb = xbl * 8 + py;       // col for wi=0
        // q = 2*hi + wi ; channel order in float4: x=c0, y=c1, z=c2, w=c3
        // (hi,wi): c0=(0,0) c1=(0,1) c2=(1,0) c3=(1,1)
        smem[(0 + px) * STRIDE + colb    ] = v.x;   // hi=0, wi=0
        smem[(0 + px) * STRIDE + colb + 4] = v.y;   // hi=0, wi=1
        smem[(4 + px) * STRIDE + colb    ] = v.z;   // hi=1, wi=0
        smem[(4 + px) * STRIDE + colb + 4] = v.w;   // hi=1, wi=1
    }

    __syncthreads();

    // ---- Store pass: 8 output rows (Yo = yb*8 + r), cols [xh*768, xh*768+768) ----
    // out float4 index: (b, Yo, Xo4) -> (b*1536 + Yo)*384 + Xo4   (1536 floats = 384 float4/row)
    const int out_base = (b * 1536 + yb * 8) * 384 + xh * 192;

    #pragma unroll
    for (int k = 0; k < 6; k++) {
        const int j  = tid + k * THREADS;    // 0..1535 = 8 rows * 192 float4
        const int r  = j / 192;              // 0..7
        const int c4 = j - r * 192;          // 0..191
        const float4 v = *reinterpret_cast<const float4*>(&smem[r * STRIDE + c4 * 4]);
        out4[out_base + r * 384 + c4] = v;
    }
}

extern "C" void kernel_launch(void* const* d_in, const int* in_sizes, int n_in,
                              void* d_out, int out_size) {
    const float4* in4 = (const float4*)d_in[0];
    float4* out4 = (float4*)d_out;
    // grid: 32 batches * 192 yb * 2 x-halves = 12288 CTAs
    weave_kernel<<<B_ * YB * 2, THREADS>>>(in4, out4);
}

// round 5
// speedup vs baseline: 1.1243x; 1.1243x over previous
#include <cuda_runtime.h>
#include <cuda_bf16.h>

// WeaveLayer permutation:
//   out[b, yb*8 + hi*4 + px, xb*8 + wi*4 + py] = in[b, yb*4 + py, xb*4 + px, q=2*hi+wi]
// in (32, 768, 768, 4) f32, out (32, 1536, 1536, 1) f32.
//
// CTA = (b, yb): reads 4 full input rows (48 KB contiguous), writes 8 full output
// rows (48 KB contiguous). smem tile in OUTPUT layout, 8 rows x 1536 floats, with
// per-row XOR swizzle (16B granularity) so load-phase scalar STS is bank-conflict-free:
//   physical_c4 = c4 ^ f(px),  f(px) = px + ((px&2)<<1)  in {0,1,6,7}
// Lane map (load): py = tid&3, px = (tid>>2)&3, xb bit0 = tid bit4 -> each warp's
// LDG covers 4 full 128B lines (perfect coalescing) AND all 32 banks per STS.

#define B_      32
#define YB      192           // 768 / 4
#define THREADS 512
#define ROWLEN  1536          // floats per smem row (= output row seg), stride = row

__global__ __launch_bounds__(THREADS, 4) void weave_kernel(
    const float4* __restrict__ in4,   // (32, 768, 768) pixels, 1 float4 each
    float4* __restrict__ out4)        // (32, 1536, 384) float4
{
    __shared__ float smem[8 * ROWLEN];   // 49152 B = 48 KB exactly

    const int bid = blockIdx.x;
    const int yb  = bid % YB;
    const int b   = bid / YB;
    const int tid = threadIdx.x;

    // ---- Load: 4 rows x 768 px = 3072 float4 ----
    const int in_base = (b * 768 + yb * 4) * 768;

    #pragma unroll
    for (int k = 0; k < 6; k++) {
        const int i  = tid + k * THREADS;      // 0..3071
        const int py = i & 3;
        const int px = (i >> 2) & 3;
        const int xb = i >> 4;                 // 0..191
        const int xl = (xb << 2) + px;         // pixel x

        const float4 v = in4[in_base + py * 768 + xl];

        const int f   = px + ((px & 2) << 1);  // {0,1,6,7}
        const int c40 = ((xb << 1) ^ f);       // (2*xb + wi=0) ^ f
        const int a00 = px * ROWLEN + (c40 << 2) + py;          // hi=0, wi=0
        const int a01 = px * ROWLEN + ((c40 ^ 1) << 2) + py;    // hi=0, wi=1

        smem[a00]              = v.x;   // q=0: hi=0, wi=0
        smem[a01]              = v.y;   // q=1: hi=0, wi=1
        smem[a00 + 4 * ROWLEN] = v.z;   // q=2: hi=1, wi=0
        smem[a01 + 4 * ROWLEN] = v.w;   // q=3: hi=1, wi=1
    }

    __syncthreads();

    // ---- Store: 8 rows x 384 float4 = 3072 float4, fully coalesced ----
    const int out_base = (b * 1536 + yb * 8) * 384;

    #pragma unroll
    for (int k = 0; k < 6; k++) {
        const int j  = tid + k * THREADS;      // 0..3071
        const int r  = j / 384;                // 0..7 (warp never straddles rows)
        const int c4 = j - r * 384;            // 0..383
        const int rp = r & 3;                  // = px of this output row
        const int f  = rp + ((rp & 2) << 1);
        const float4 v = *reinterpret_cast<const float4*>(
            &smem[r * ROWLEN + ((c4 ^ f) << 2)]);
        out4[out_base + r * 384 + c4] = v;
    }
}

extern "C" void kernel_launch(void* const* d_in, const int* in_sizes, int n_in,
                              void* d_out, int out_size) {
    const float4* in4 = (const float4*)d_in[0];
    float4* out4 = (float4*)d_out;
    weave_kernel<<<B_ * YB, THREADS>>>(in4, out4);
}